// round 2
// baseline (speedup 1.0000x reference)
#include <cuda_runtime.h>
#include <math.h>

// ---------------------------------------------------------------------------
// Problem constants
//   D = 512, H = 8 (head dim 64), B = 64 studies, N = 131072 cells.
//   Padded layout: row r = n*64 + g  (n = position within study, g = study).
//   max_n is data-dependent -> computed on device; CAP is a safe upper bound.
// ---------------------------------------------------------------------------
#define CAP       2560
#define ROWS_CAP  (CAP * 64)   // 163840

__device__ int g_maxn;
__device__ int g_starts[65];
__device__ int g_counts[64];

// Scratch (device globals: allocation-free rule). ~2.7 GB total.
__device__ float g_X  [(size_t)ROWS_CAP * 512];   // input / Y1 (post-LN1)
__device__ float g_QKV[(size_t)ROWS_CAP * 1536];
__device__ float g_ATT[(size_t)ROWS_CAP * 512];   // attn out, later final X2
__device__ float g_TMP[(size_t)ROWS_CAP * 512];
__device__ float g_HID[(size_t)ROWS_CAP * 1024];

// ---------------------------------------------------------------------------
// Meta: starts/counts/max_n from the (sorted) study index array.
// ---------------------------------------------------------------------------
__global__ void k_meta(const int* __restrict__ idx, int N) {
    __shared__ int st[65];
    __shared__ int smax;
    int t = threadIdx.x;
    if (t == 0) smax = 0;
    if (t <= 64) {
        if (t == 64) {
            st[64] = N;
        } else {
            int lo = 0, hi = N;
            while (lo < hi) { int mid = (lo + hi) >> 1; if (idx[mid] < t) lo = mid + 1; else hi = mid; }
            st[t] = lo;
        }
    }
    __syncthreads();
    if (t < 64) {
        int c = st[t + 1] - st[t];
        g_starts[t] = st[t];
        g_counts[t] = c;
        atomicMax(&smax, c);
    }
    if (t == 64) g_starts[64] = N;
    __syncthreads();
    if (t == 0) g_maxn = (smax < CAP) ? smax : CAP;
}

// Zero only the padding rows (valid rows are fully overwritten by scatter).
__global__ void k_zeropad() {
    int r = blockIdx.x;
    int n = r >> 6, g = r & 63;
    if (n >= g_maxn || n < g_counts[g]) return;
    ((float4*)(g_X + (size_t)r * 512))[threadIdx.x] = make_float4(0.f, 0.f, 0.f, 0.f);
}

// Scatter: embedding row i -> X row (i - starts[g])*64 + g. (indexes sorted)
__global__ void k_scatter(const float* __restrict__ emb, const int* __restrict__ idx) {
    int i = blockIdx.x;
    int g = idx[i];
    int n = i - g_starts[g];
    const float4* s = (const float4*)(emb + (size_t)i * 512);
    float4*       d = (float4*)(g_X + (size_t)(n * 64 + g) * 512);
    d[threadIdx.x] = s[threadIdx.x];
}

// ---------------------------------------------------------------------------
// NT GEMM: C[M, Nc] = A[M, K] * B[Nc, K]^T + bias (+resid) (relu optional).
// 128x128 tile, BK=8, 256 threads, 8x8 per-thread microtile. M = g_maxn*64.
// ---------------------------------------------------------------------------
__global__ __launch_bounds__(256, 2)
void k_gemm(const float* __restrict__ A, const float* __restrict__ Bw,
            const float* __restrict__ bias, const float* __restrict__ resid,
            float* __restrict__ C, int Ncols, int K, int relu)
{
    int M    = g_maxn * 64;
    int row0 = blockIdx.y * 128;
    if (row0 >= M) return;
    int col0 = blockIdx.x * 128;

    __shared__ float As[8][128];
    __shared__ float Bs[8][128];

    int tid = threadIdx.x;
    int tr  = (tid >> 4) << 3;   // 0..120
    int tc  = (tid & 15) << 3;   // 0..120

    float acc[8][8];
#pragma unroll
    for (int i = 0; i < 8; i++)
#pragma unroll
        for (int j = 0; j < 8; j++) acc[i][j] = 0.f;

    int lr = tid >> 1;           // 0..127
    int lc = (tid & 1) << 2;     // 0 or 4
    const float* Ap = A  + (size_t)(row0 + lr) * K + lc;
    const float* Bp = Bw + (size_t)(col0 + lr) * K + lc;
    const bool a_ok = (row0 + lr) < M;

    for (int k0 = 0; k0 < K; k0 += 8) {
        float4 av = a_ok ? *(const float4*)(Ap + k0) : make_float4(0.f, 0.f, 0.f, 0.f);
        float4 bv = *(const float4*)(Bp + k0);
        As[lc + 0][lr] = av.x; As[lc + 1][lr] = av.y; As[lc + 2][lr] = av.z; As[lc + 3][lr] = av.w;
        Bs[lc + 0][lr] = bv.x; Bs[lc + 1][lr] = bv.y; Bs[lc + 2][lr] = bv.z; Bs[lc + 3][lr] = bv.w;
        __syncthreads();
#pragma unroll
        for (int k = 0; k < 8; k++) {
            float a[8], b[8];
#pragma unroll
            for (int i = 0; i < 8; i++) a[i] = As[k][tr + i];
#pragma unroll
            for (int j = 0; j < 8; j++) b[j] = Bs[k][tc + j];
#pragma unroll
            for (int i = 0; i < 8; i++)
#pragma unroll
                for (int j = 0; j < 8; j++)
                    acc[i][j] = fmaf(a[i], b[j], acc[i][j]);
        }
        __syncthreads();
    }

#pragma unroll
    for (int i = 0; i < 8; i++) {
        int r = row0 + tr + i;
        if (r >= M) continue;
        float* Cr = C + (size_t)r * Ncols;
        const float* Rr = resid ? (resid + (size_t)r * Ncols) : (const float*)0;
#pragma unroll
        for (int j = 0; j < 8; j += 4) {
            int c = col0 + tc + j;
            float4 v;
            v.x = acc[i][j + 0] + bias[c + 0];
            v.y = acc[i][j + 1] + bias[c + 1];
            v.z = acc[i][j + 2] + bias[c + 2];
            v.w = acc[i][j + 3] + bias[c + 3];
            if (Rr) {
                float4 rv = *(const float4*)(Rr + c);
                v.x += rv.x; v.y += rv.y; v.z += rv.z; v.w += rv.w;
            }
            if (relu) {
                v.x = fmaxf(v.x, 0.f); v.y = fmaxf(v.y, 0.f);
                v.z = fmaxf(v.z, 0.f); v.w = fmaxf(v.w, 0.f);
            }
            *(float4*)(Cr + c) = v;
        }
    }
}

// ---------------------------------------------------------------------------
// Attention: one block per (position n, head h). seq = 64 studies, e = 64.
// kpm: key t masked at position n iff counts[t] <= n.
// 48 KB smem: Qt/Kt transposed [e][s] (conflict-free reads), V [t][e].
// ---------------------------------------------------------------------------
__global__ __launch_bounds__(256)
void k_attn(const float* __restrict__ QKV, float* __restrict__ ATT) {
    int n = blockIdx.x;
    if (n >= g_maxn) return;
    int h = blockIdx.y;

    __shared__ float Qt[64][64];
    __shared__ float Kt[64][64];
    __shared__ float V [64][64];

    int tid = threadIdx.x;
    size_t base = (size_t)n * 64 * 1536 + (size_t)h * 64;
    for (int idx = tid; idx < 4096; idx += 256) {
        int s = idx >> 6, e = idx & 63;
        size_t rb = base + (size_t)s * 1536 + e;
        Qt[e][s] = QKV[rb];
        Kt[e][s] = QKV[rb + 512];
        V [s][e] = QKV[rb + 1024];
    }
    __syncthreads();

    int s  = tid >> 2;       // query study (row)
    int qd = tid & 3;        // quarter
    int t0 = qd << 4;        // this thread's 16 key columns

    float acc[16];
#pragma unroll
    for (int j = 0; j < 16; j++) acc[j] = 0.f;

#pragma unroll 4
    for (int e = 0; e < 64; e++) {
        float  qv = Qt[e][s];
        float4 k0 = *(const float4*)&Kt[e][t0 + 0];
        float4 k1 = *(const float4*)&Kt[e][t0 + 4];
        float4 k2 = *(const float4*)&Kt[e][t0 + 8];
        float4 k3 = *(const float4*)&Kt[e][t0 + 12];
        acc[0]  = fmaf(qv, k0.x, acc[0]);  acc[1]  = fmaf(qv, k0.y, acc[1]);
        acc[2]  = fmaf(qv, k0.z, acc[2]);  acc[3]  = fmaf(qv, k0.w, acc[3]);
        acc[4]  = fmaf(qv, k1.x, acc[4]);  acc[5]  = fmaf(qv, k1.y, acc[5]);
        acc[6]  = fmaf(qv, k1.z, acc[6]);  acc[7]  = fmaf(qv, k1.w, acc[7]);
        acc[8]  = fmaf(qv, k2.x, acc[8]);  acc[9]  = fmaf(qv, k2.y, acc[9]);
        acc[10] = fmaf(qv, k2.z, acc[10]); acc[11] = fmaf(qv, k2.w, acc[11]);
        acc[12] = fmaf(qv, k3.x, acc[12]); acc[13] = fmaf(qv, k3.y, acc[13]);
        acc[14] = fmaf(qv, k3.z, acc[14]); acc[15] = fmaf(qv, k3.w, acc[15]);
    }

    // scale + key-padding mask + softmax over 64 keys (4 lanes share a row)
    float mx = -1e30f;
#pragma unroll
    for (int j = 0; j < 16; j++) {
        float v = acc[j] * 0.125f;          // 1/sqrt(64)
        if (g_counts[t0 + j] <= n) v = -1e30f;
        acc[j] = v;
        mx = fmaxf(mx, v);
    }
    mx = fmaxf(mx, __shfl_xor_sync(0xffffffffu, mx, 1, 4));
    mx = fmaxf(mx, __shfl_xor_sync(0xffffffffu, mx, 2, 4));
    float sum = 0.f;
#pragma unroll
    for (int j = 0; j < 16; j++) { float p = __expf(acc[j] - mx); acc[j] = p; sum += p; }
    sum += __shfl_xor_sync(0xffffffffu, sum, 1, 4);
    sum += __shfl_xor_sync(0xffffffffu, sum, 2, 4);
    float inv = 1.f / sum;
#pragma unroll
    for (int j = 0; j < 16; j++) acc[j] *= inv;

    // AV: this thread owns out[s][e0 .. e0+15]
    float o[16];
#pragma unroll
    for (int j = 0; j < 16; j++) o[j] = 0.f;
    int e0 = qd << 4;
#pragma unroll
    for (int tq = 0; tq < 4; tq++) {
#pragma unroll
        for (int j2 = 0; j2 < 16; j2++) {
            float a = __shfl_sync(0xffffffffu, acc[j2], tq, 4);
            const float* vr = &V[tq * 16 + j2][e0];
            float4 v0 = *(const float4*)(vr + 0);
            float4 v1 = *(const float4*)(vr + 4);
            float4 v2 = *(const float4*)(vr + 8);
            float4 v3 = *(const float4*)(vr + 12);
            o[0]  = fmaf(a, v0.x, o[0]);  o[1]  = fmaf(a, v0.y, o[1]);
            o[2]  = fmaf(a, v0.z, o[2]);  o[3]  = fmaf(a, v0.w, o[3]);
            o[4]  = fmaf(a, v1.x, o[4]);  o[5]  = fmaf(a, v1.y, o[5]);
            o[6]  = fmaf(a, v1.z, o[6]);  o[7]  = fmaf(a, v1.w, o[7]);
            o[8]  = fmaf(a, v2.x, o[8]);  o[9]  = fmaf(a, v2.y, o[9]);
            o[10] = fmaf(a, v2.z, o[10]); o[11] = fmaf(a, v2.w, o[11]);
            o[12] = fmaf(a, v3.x, o[12]); o[13] = fmaf(a, v3.y, o[13]);
            o[14] = fmaf(a, v3.z, o[14]); o[15] = fmaf(a, v3.w, o[15]);
        }
    }

    float* op = ATT + (size_t)(n * 64 + s) * 512 + (size_t)h * 64 + e0;
    *(float4*)(op + 0)  = make_float4(o[0],  o[1],  o[2],  o[3]);
    *(float4*)(op + 4)  = make_float4(o[4],  o[5],  o[6],  o[7]);
    *(float4*)(op + 8)  = make_float4(o[8],  o[9],  o[10], o[11]);
    *(float4*)(op + 12) = make_float4(o[12], o[13], o[14], o[15]);
}

// ---------------------------------------------------------------------------
// LayerNorm over D=512 per row (input already contains residual sum).
// ---------------------------------------------------------------------------
__global__ void k_ln(const float* __restrict__ in, const float* __restrict__ gam,
                     const float* __restrict__ bet, float* __restrict__ outp) {
    int r = blockIdx.x;
    if (r >= g_maxn * 64) return;
    int t = threadIdx.x;  // 128
    float4 v = ((const float4*)(in + (size_t)r * 512))[t];
    float s  = v.x + v.y + v.z + v.w;
    float ss = fmaf(v.x, v.x, fmaf(v.y, v.y, fmaf(v.z, v.z, v.w * v.w)));
#pragma unroll
    for (int o = 16; o; o >>= 1) {
        s  += __shfl_xor_sync(0xffffffffu, s,  o);
        ss += __shfl_xor_sync(0xffffffffu, ss, o);
    }
    __shared__ float sh[8];
    if ((t & 31) == 0) { sh[t >> 5] = s; sh[4 + (t >> 5)] = ss; }
    __syncthreads();
    s  = sh[0] + sh[1] + sh[2] + sh[3];
    ss = sh[4] + sh[5] + sh[6] + sh[7];
    float mean = s * (1.f / 512.f);
    float var  = ss * (1.f / 512.f) - mean * mean;
    float inv  = rsqrtf(var + 1e-5f);
    float4 g4 = ((const float4*)gam)[t];
    float4 b4 = ((const float4*)bet)[t];
    float4 o4;
    o4.x = (v.x - mean) * inv * g4.x + b4.x;
    o4.y = (v.y - mean) * inv * g4.y + b4.y;
    o4.z = (v.z - mean) * inv * g4.z + b4.z;
    o4.w = (v.w - mean) * inv * g4.w + b4.w;
    ((float4*)(outp + (size_t)r * 512))[t] = o4;
}

// ---------------------------------------------------------------------------
// Mean pool over positions: out[g][d] = mean_n X2[(n*64+g)*512 + d]
// ---------------------------------------------------------------------------
__global__ void k_pool(const float* __restrict__ Xf, float* __restrict__ out) {
    int g = blockIdx.x;
    int d = threadIdx.x;  // 512
    int mx = g_maxn;
    const float* p = Xf + (size_t)g * 512 + d;
    const size_t stride = 64 * 512;
    float s0 = 0.f, s1 = 0.f, s2 = 0.f, s3 = 0.f;
    int n = 0;
    for (; n + 4 <= mx; n += 4) {
        s0 += p[(size_t)(n + 0) * stride];
        s1 += p[(size_t)(n + 1) * stride];
        s2 += p[(size_t)(n + 2) * stride];
        s3 += p[(size_t)(n + 3) * stride];
    }
    for (; n < mx; n++) s0 += p[(size_t)n * stride];
    out[g * 512 + d] = (s0 + s1 + s2 + s3) / (float)mx;
}

// ---------------------------------------------------------------------------
// Launch
// ---------------------------------------------------------------------------
extern "C" void kernel_launch(void* const* d_in, const int* in_sizes, int n_in,
                              void* d_out, int out_size) {
    const float* emb  = (const float*)d_in[0];
    const int*   sidx = (const int*)  d_in[1];
    const float* W_in = (const float*)d_in[2];
    const float* b_in = (const float*)d_in[3];
    const float* W_o  = (const float*)d_in[4];
    const float* b_o  = (const float*)d_in[5];
    const float* ln1g = (const float*)d_in[6];
    const float* ln1b = (const float*)d_in[7];
    const float* W1   = (const float*)d_in[8];
    const float* b1   = (const float*)d_in[9];
    const float* W2   = (const float*)d_in[10];
    const float* b2   = (const float*)d_in[11];
    const float* ln2g = (const float*)d_in[12];
    const float* ln2b = (const float*)d_in[13];
    float* out = (float*)d_out;
    (void)n_in; (void)out_size;

    int N = in_sizes[0] / 512;

    float *pX, *pQKV, *pATT, *pTMP, *pHID;
    cudaGetSymbolAddress((void**)&pX,   g_X);
    cudaGetSymbolAddress((void**)&pQKV, g_QKV);
    cudaGetSymbolAddress((void**)&pATT, g_ATT);
    cudaGetSymbolAddress((void**)&pTMP, g_TMP);
    cudaGetSymbolAddress((void**)&pHID, g_HID);

    const int GY = ROWS_CAP / 128;  // 1280

    k_meta<<<1, 128>>>(sidx, N);
    k_zeropad<<<ROWS_CAP, 128>>>();
    k_scatter<<<N, 128>>>(emb, sidx);

    // QKV = X @ W_in^T + b_in                       [M, 1536]
    k_gemm<<<dim3(12, GY), 256>>>(pX, W_in, b_in, nullptr, pQKV, 1536, 512, 0);

    // attention per (n, h)                          -> ATT [M, 512]
    k_attn<<<dim3(CAP, 8), 256>>>(pQKV, pATT);

    // TMP = ATT @ W_o^T + b_o + X (residual fused)  [M, 512]
    k_gemm<<<dim3(4, GY), 256>>>(pATT, W_o, b_o, pX, pTMP, 512, 512, 0);

    // Y1 = LN1(TMP)  (stored into X buffer)
    k_ln<<<ROWS_CAP, 128>>>(pTMP, ln1g, ln1b, pX);

    // HID = relu(Y1 @ W1^T + b1)                    [M, 1024]
    k_gemm<<<dim3(8, GY), 256>>>(pX, W1, b1, nullptr, pHID, 1024, 512, 1);

    // TMP = HID @ W2^T + b2 + Y1 (residual fused)   [M, 512]
    k_gemm<<<dim3(4, GY), 256>>>(pHID, W2, b2, pX, pTMP, 512, 1024, 0);

    // X2 = LN2(TMP)  (stored into ATT buffer)
    k_ln<<<ROWS_CAP, 128>>>(pTMP, ln2g, ln2b, pATT);

    // out[g][d] = mean over positions
    k_pool<<<64, 512>>>(pATT, out);
}

// round 4
// speedup vs baseline: 1.7121x; 1.7121x over previous
#include <cuda_runtime.h>
#include <math.h>
#include <stdint.h>

// ---------------------------------------------------------------------------
// Problem: D=512, H=8 (e=64), B=64 studies, N=131072 cells.
// Padded layout: row r = n*64 + g. max_n data-dependent; CAP upper bound.
// ---------------------------------------------------------------------------
#define CAP       2560
#define ROWS_CAP  (CAP * 64)   // 163840

__device__ int g_maxn;
__device__ int g_starts[65];
__device__ int g_counts[64];

__device__ float g_X  [(size_t)ROWS_CAP * 512];
__device__ float g_QKV[(size_t)ROWS_CAP * 1536];
__device__ float g_ATT[(size_t)ROWS_CAP * 512];
__device__ float g_TMP[(size_t)ROWS_CAP * 512];
__device__ float g_HID[(size_t)ROWS_CAP * 1024];

// ---------------------------------------------------------------------------
// Meta / scatter / zeropad (proven)
// ---------------------------------------------------------------------------
__global__ void k_meta(const int* __restrict__ idx, int N) {
    __shared__ int st[65];
    __shared__ int smax;
    int t = threadIdx.x;
    if (t == 0) smax = 0;
    if (t <= 64) {
        if (t == 64) st[64] = N;
        else {
            int lo = 0, hi = N;
            while (lo < hi) { int mid = (lo + hi) >> 1; if (idx[mid] < t) lo = mid + 1; else hi = mid; }
            st[t] = lo;
        }
    }
    __syncthreads();
    if (t < 64) {
        int c = st[t + 1] - st[t];
        g_starts[t] = st[t];
        g_counts[t] = c;
        atomicMax(&smax, c);
    }
    if (t == 64) g_starts[64] = N;
    __syncthreads();
    if (t == 0) g_maxn = (smax < CAP) ? smax : CAP;
}

__global__ void k_zeropad() {
    int r = blockIdx.x;
    int n = r >> 6, g = r & 63;
    if (n >= g_maxn || n < g_counts[g]) return;
    ((float4*)(g_X + (size_t)r * 512))[threadIdx.x] = make_float4(0.f, 0.f, 0.f, 0.f);
}

__global__ void k_scatter(const float* __restrict__ emb, const int* __restrict__ idx) {
    int i = blockIdx.x;
    int g = idx[i];
    int n = i - g_starts[g];
    const float4* s = (const float4*)(emb + (size_t)i * 512);
    float4*       d = (float4*)(g_X + (size_t)(n * 64 + g) * 512);
    d[threadIdx.x] = s[threadIdx.x];
}

// ---------------------------------------------------------------------------
// tf32 tensor-core GEMM via mma.sync (baseline PTX, works on compute_103).
// C[M,Nc] = A[M,K] * Bw[Nc,K]^T + bias (+resid) (relu optional)
// BM=BN=128, BK=32. 8 warps; warp tile 64x32 (4x4 m16n8k8). Double-buffered.
// Smem rows padded to 36 floats -> conflict-free fragment loads.
// ---------------------------------------------------------------------------
#define SROW 36
#define TILE_U32 (128 * SROW)                 // 4608 words per tile
#define TG_SMEM_BYTES (4u * TILE_U32 * 4u)    // 73728 B

__device__ __forceinline__ uint32_t f2tf32(float f) {
    uint32_t r;
    asm("cvt.rna.tf32.f32 %0, %1;" : "=r"(r) : "f"(f));
    return r;
}
__device__ __forceinline__ void mma_tf32(float c[4],
                                         uint32_t a0, uint32_t a1, uint32_t a2, uint32_t a3,
                                         uint32_t b0, uint32_t b1) {
    asm volatile(
        "mma.sync.aligned.m16n8k8.row.col.f32.tf32.tf32.f32 "
        "{%0,%1,%2,%3}, {%4,%5,%6,%7}, {%8,%9}, {%0,%1,%2,%3};"
        : "+f"(c[0]), "+f"(c[1]), "+f"(c[2]), "+f"(c[3])
        : "r"(a0), "r"(a1), "r"(a2), "r"(a3), "r"(b0), "r"(b1));
}

__global__ __launch_bounds__(256, 2)
void k_tgemm(const float* __restrict__ A, const float* __restrict__ Bw,
             const float* __restrict__ bias, const float* __restrict__ resid,
             float* __restrict__ C, int Ncols, int K, int relu)
{
    int M = g_maxn * 64;
    int row0 = blockIdx.y * 128;
    if (row0 >= M) return;
    int col0 = blockIdx.x * 128;

    int tid  = threadIdx.x;
    int lane = tid & 31;
    int wid  = tid >> 5;
    int wm   = wid & 1;        // 2 warp rows (64 rows each)
    int wn   = wid >> 1;       // 4 warp cols (32 cols each)
    int g    = lane >> 2;      // group id 0..7
    int tg   = lane & 3;       // thread-in-group

    extern __shared__ uint32_t sm[];
    uint32_t* Asb[2] = { sm,                sm + TILE_U32 };
    uint32_t* Bsb[2] = { sm + 2 * TILE_U32, sm + 3 * TILE_U32 };

    float c[4][4][4];
#pragma unroll
    for (int i = 0; i < 4; i++)
#pragma unroll
        for (int j = 0; j < 4; j++)
#pragma unroll
            for (int k = 0; k < 4; k++) c[i][j][k] = 0.f;

    // per-thread tile-load coords: 4 iters, idx = tid+256*i -> row 0..127, c4 0..7
    const float* Abase = A  + (size_t)row0 * K;
    const float* Bbase = Bw + (size_t)col0 * K;

    // prologue: tile 0 -> buffer 0
#pragma unroll
    for (int i = 0; i < 4; i++) {
        int idx = tid + 256 * i;
        int row = idx >> 3, c4 = idx & 7;
        float4 va = *(const float4*)(Abase + (size_t)row * K + c4 * 4);
        float4 vb = *(const float4*)(Bbase + (size_t)row * K + c4 * 4);
        uint32_t* pa = Asb[0] + row * SROW + c4 * 4;
        uint32_t* pb = Bsb[0] + row * SROW + c4 * 4;
        pa[0] = f2tf32(va.x); pa[1] = f2tf32(va.y); pa[2] = f2tf32(va.z); pa[3] = f2tf32(va.w);
        pb[0] = f2tf32(vb.x); pb[1] = f2tf32(vb.y); pb[2] = f2tf32(vb.z); pb[3] = f2tf32(vb.w);
    }
    __syncthreads();

    const int KT = K >> 5;
    float4 rA[4], rB[4];

    for (int kt = 0; kt < KT; kt++) {
        int cur = kt & 1;
        bool pf = (kt + 1 < KT);
        if (pf) {
            int ko = (kt + 1) * 32;
#pragma unroll
            for (int i = 0; i < 4; i++) {
                int idx = tid + 256 * i;
                int row = idx >> 3, c4 = idx & 7;
                rA[i] = *(const float4*)(Abase + (size_t)row * K + ko + c4 * 4);
                rB[i] = *(const float4*)(Bbase + (size_t)row * K + ko + c4 * 4);
            }
        }

        const uint32_t* Acur = Asb[cur];
        const uint32_t* Bcur = Bsb[cur];
#pragma unroll
        for (int kk = 0; kk < 4; kk++) {
            uint32_t af[4][4];
#pragma unroll
            for (int mt = 0; mt < 4; mt++) {
                const uint32_t* p = Acur + (wm * 64 + mt * 16 + g) * SROW + kk * 8 + tg;
                af[mt][0] = p[0];
                af[mt][1] = p[8 * SROW];
                af[mt][2] = p[4];
                af[mt][3] = p[8 * SROW + 4];
            }
#pragma unroll
            for (int nt = 0; nt < 4; nt++) {
                const uint32_t* q = Bcur + (wn * 32 + nt * 8 + g) * SROW + kk * 8 + tg;
                uint32_t b0 = q[0];
                uint32_t b1 = q[4];
#pragma unroll
                for (int mt = 0; mt < 4; mt++)
                    mma_tf32(c[mt][nt], af[mt][0], af[mt][1], af[mt][2], af[mt][3], b0, b1);
            }
        }

        if (pf) {
            int nb = cur ^ 1;
#pragma unroll
            for (int i = 0; i < 4; i++) {
                int idx = tid + 256 * i;
                int row = idx >> 3, c4 = idx & 7;
                uint32_t* pa = Asb[nb] + row * SROW + c4 * 4;
                uint32_t* pb = Bsb[nb] + row * SROW + c4 * 4;
                pa[0] = f2tf32(rA[i].x); pa[1] = f2tf32(rA[i].y);
                pa[2] = f2tf32(rA[i].z); pa[3] = f2tf32(rA[i].w);
                pb[0] = f2tf32(rB[i].x); pb[1] = f2tf32(rB[i].y);
                pb[2] = f2tf32(rB[i].z); pb[3] = f2tf32(rB[i].w);
            }
        }
        __syncthreads();
    }

    // epilogue: bias (+resid) (relu), float2 stores
#pragma unroll
    for (int mt = 0; mt < 4; mt++) {
        int r0 = row0 + wm * 64 + mt * 16 + g;
        int r1 = r0 + 8;
#pragma unroll
        for (int nt = 0; nt < 4; nt++) {
            int cc = col0 + wn * 32 + nt * 8 + 2 * tg;
            float2 bv = *(const float2*)(bias + cc);
            if (r0 < M) {
                float2 o = make_float2(c[mt][nt][0] + bv.x, c[mt][nt][1] + bv.y);
                if (resid) {
                    float2 rv = *(const float2*)(resid + (size_t)r0 * Ncols + cc);
                    o.x += rv.x; o.y += rv.y;
                }
                if (relu) { o.x = fmaxf(o.x, 0.f); o.y = fmaxf(o.y, 0.f); }
                *(float2*)(C + (size_t)r0 * Ncols + cc) = o;
            }
            if (r1 < M) {
                float2 o = make_float2(c[mt][nt][2] + bv.x, c[mt][nt][3] + bv.y);
                if (resid) {
                    float2 rv = *(const float2*)(resid + (size_t)r1 * Ncols + cc);
                    o.x += rv.x; o.y += rv.y;
                }
                if (relu) { o.x = fmaxf(o.x, 0.f); o.y = fmaxf(o.y, 0.f); }
                *(float2*)(C + (size_t)r1 * Ncols + cc) = o;
            }
        }
    }
}

// ---------------------------------------------------------------------------
// Attention (proven): one block per (position n, head h).
// ---------------------------------------------------------------------------
__global__ __launch_bounds__(256)
void k_attn(const float* __restrict__ QKV, float* __restrict__ ATT) {
    int n = blockIdx.x;
    if (n >= g_maxn) return;
    int h = blockIdx.y;

    __shared__ float Qt[64][64];
    __shared__ float Kt[64][64];
    __shared__ float V [64][64];

    int tid = threadIdx.x;
    size_t base = (size_t)n * 64 * 1536 + (size_t)h * 64;
    for (int idx = tid; idx < 4096; idx += 256) {
        int s = idx >> 6, e = idx & 63;
        size_t rb = base + (size_t)s * 1536 + e;
        Qt[e][s] = QKV[rb];
        Kt[e][s] = QKV[rb + 512];
        V [s][e] = QKV[rb + 1024];
    }
    __syncthreads();

    int s  = tid >> 2;
    int qd = tid & 3;
    int t0 = qd << 4;

    float acc[16];
#pragma unroll
    for (int j = 0; j < 16; j++) acc[j] = 0.f;

#pragma unroll 4
    for (int e = 0; e < 64; e++) {
        float  qv = Qt[e][s];
        float4 k0 = *(const float4*)&Kt[e][t0 + 0];
        float4 k1 = *(const float4*)&Kt[e][t0 + 4];
        float4 k2 = *(const float4*)&Kt[e][t0 + 8];
        float4 k3 = *(const float4*)&Kt[e][t0 + 12];
        acc[0]  = fmaf(qv, k0.x, acc[0]);  acc[1]  = fmaf(qv, k0.y, acc[1]);
        acc[2]  = fmaf(qv, k0.z, acc[2]);  acc[3]  = fmaf(qv, k0.w, acc[3]);
        acc[4]  = fmaf(qv, k1.x, acc[4]);  acc[5]  = fmaf(qv, k1.y, acc[5]);
        acc[6]  = fmaf(qv, k1.z, acc[6]);  acc[7]  = fmaf(qv, k1.w, acc[7]);
        acc[8]  = fmaf(qv, k2.x, acc[8]);  acc[9]  = fmaf(qv, k2.y, acc[9]);
        acc[10] = fmaf(qv, k2.z, acc[10]); acc[11] = fmaf(qv, k2.w, acc[11]);
        acc[12] = fmaf(qv, k3.x, acc[12]); acc[13] = fmaf(qv, k3.y, acc[13]);
        acc[14] = fmaf(qv, k3.z, acc[14]); acc[15] = fmaf(qv, k3.w, acc[15]);
    }

    float mx = -1e30f;
#pragma unroll
    for (int j = 0; j < 16; j++) {
        float v = acc[j] * 0.125f;
        if (g_counts[t0 + j] <= n) v = -1e30f;
        acc[j] = v;
        mx = fmaxf(mx, v);
    }
    mx = fmaxf(mx, __shfl_xor_sync(0xffffffffu, mx, 1, 4));
    mx = fmaxf(mx, __shfl_xor_sync(0xffffffffu, mx, 2, 4));
    float sum = 0.f;
#pragma unroll
    for (int j = 0; j < 16; j++) { float p = __expf(acc[j] - mx); acc[j] = p; sum += p; }
    sum += __shfl_xor_sync(0xffffffffu, sum, 1, 4);
    sum += __shfl_xor_sync(0xffffffffu, sum, 2, 4);
    float inv = 1.f / sum;
#pragma unroll
    for (int j = 0; j < 16; j++) acc[j] *= inv;

    float o[16];
#pragma unroll
    for (int j = 0; j < 16; j++) o[j] = 0.f;
    int e0 = qd << 4;
#pragma unroll
    for (int tq = 0; tq < 4; tq++) {
#pragma unroll
        for (int j2 = 0; j2 < 16; j2++) {
            float a = __shfl_sync(0xffffffffu, acc[j2], tq, 4);
            const float* vr = &V[tq * 16 + j2][e0];
            float4 v0 = *(const float4*)(vr + 0);
            float4 v1 = *(const float4*)(vr + 4);
            float4 v2 = *(const float4*)(vr + 8);
            float4 v3 = *(const float4*)(vr + 12);
            o[0]  = fmaf(a, v0.x, o[0]);  o[1]  = fmaf(a, v0.y, o[1]);
            o[2]  = fmaf(a, v0.z, o[2]);  o[3]  = fmaf(a, v0.w, o[3]);
            o[4]  = fmaf(a, v1.x, o[4]);  o[5]  = fmaf(a, v1.y, o[5]);
            o[6]  = fmaf(a, v1.z, o[6]);  o[7]  = fmaf(a, v1.w, o[7]);
            o[8]  = fmaf(a, v2.x, o[8]);  o[9]  = fmaf(a, v2.y, o[9]);
            o[10] = fmaf(a, v2.z, o[10]); o[11] = fmaf(a, v2.w, o[11]);
            o[12] = fmaf(a, v3.x, o[12]); o[13] = fmaf(a, v3.y, o[13]);
            o[14] = fmaf(a, v3.z, o[14]); o[15] = fmaf(a, v3.w, o[15]);
        }
    }

    float* op = ATT + (size_t)(n * 64 + s) * 512 + (size_t)h * 64 + e0;
    *(float4*)(op + 0)  = make_float4(o[0],  o[1],  o[2],  o[3]);
    *(float4*)(op + 4)  = make_float4(o[4],  o[5],  o[6],  o[7]);
    *(float4*)(op + 8)  = make_float4(o[8],  o[9],  o[10], o[11]);
    *(float4*)(op + 12) = make_float4(o[12], o[13], o[14], o[15]);
}

// ---------------------------------------------------------------------------
// LayerNorm + pool (proven)
// ---------------------------------------------------------------------------
__global__ void k_ln(const float* __restrict__ in, const float* __restrict__ gam,
                     const float* __restrict__ bet, float* __restrict__ outp) {
    int r = blockIdx.x;
    if (r >= g_maxn * 64) return;
    int t = threadIdx.x;
    float4 v = ((const float4*)(in + (size_t)r * 512))[t];
    float s  = v.x + v.y + v.z + v.w;
    float ss = fmaf(v.x, v.x, fmaf(v.y, v.y, fmaf(v.z, v.z, v.w * v.w)));
#pragma unroll
    for (int o = 16; o; o >>= 1) {
        s  += __shfl_xor_sync(0xffffffffu, s,  o);
        ss += __shfl_xor_sync(0xffffffffu, ss, o);
    }
    __shared__ float sh[8];
    if ((t & 31) == 0) { sh[t >> 5] = s; sh[4 + (t >> 5)] = ss; }
    __syncthreads();
    s  = sh[0] + sh[1] + sh[2] + sh[3];
    ss = sh[4] + sh[5] + sh[6] + sh[7];
    float mean = s * (1.f / 512.f);
    float var  = ss * (1.f / 512.f) - mean * mean;
    float inv  = rsqrtf(var + 1e-5f);
    float4 g4 = ((const float4*)gam)[t];
    float4 b4 = ((const float4*)bet)[t];
    float4 o4;
    o4.x = (v.x - mean) * inv * g4.x + b4.x;
    o4.y = (v.y - mean) * inv * g4.y + b4.y;
    o4.z = (v.z - mean) * inv * g4.z + b4.z;
    o4.w = (v.w - mean) * inv * g4.w + b4.w;
    ((float4*)(outp + (size_t)r * 512))[t] = o4;
}

__global__ void k_pool(const float* __restrict__ Xf, float* __restrict__ out) {
    int g = blockIdx.x;
    int d = threadIdx.x;
    int mx = g_maxn;
    const float* p = Xf + (size_t)g * 512 + d;
    const size_t stride = 64 * 512;
    float s0 = 0.f, s1 = 0.f, s2 = 0.f, s3 = 0.f;
    int n = 0;
    for (; n + 4 <= mx; n += 4) {
        s0 += p[(size_t)(n + 0) * stride];
        s1 += p[(size_t)(n + 1) * stride];
        s2 += p[(size_t)(n + 2) * stride];
        s3 += p[(size_t)(n + 3) * stride];
    }
    for (; n < mx; n++) s0 += p[(size_t)n * stride];
    out[g * 512 + d] = (s0 + s1 + s2 + s3) / (float)mx;
}

// ---------------------------------------------------------------------------
// Launch
// ---------------------------------------------------------------------------
extern "C" void kernel_launch(void* const* d_in, const int* in_sizes, int n_in,
                              void* d_out, int out_size) {
    const float* emb  = (const float*)d_in[0];
    const int*   sidx = (const int*)  d_in[1];
    const float* W_in = (const float*)d_in[2];
    const float* b_in = (const float*)d_in[3];
    const float* W_o  = (const float*)d_in[4];
    const float* b_o  = (const float*)d_in[5];
    const float* ln1g = (const float*)d_in[6];
    const float* ln1b = (const float*)d_in[7];
    const float* W1   = (const float*)d_in[8];
    const float* b1   = (const float*)d_in[9];
    const float* W2   = (const float*)d_in[10];
    const float* b2   = (const float*)d_in[11];
    const float* ln2g = (const float*)d_in[12];
    const float* ln2b = (const float*)d_in[13];
    float* out = (float*)d_out;
    (void)n_in; (void)out_size;

    int N = in_sizes[0] / 512;

    float *pX, *pQKV, *pATT, *pTMP, *pHID;
    cudaGetSymbolAddress((void**)&pX,   g_X);
    cudaGetSymbolAddress((void**)&pQKV, g_QKV);
    cudaGetSymbolAddress((void**)&pATT, g_ATT);
    cudaGetSymbolAddress((void**)&pTMP, g_TMP);
    cudaGetSymbolAddress((void**)&pHID, g_HID);

    cudaFuncSetAttribute(k_tgemm, cudaFuncAttributeMaxDynamicSharedMemorySize,
                         (int)TG_SMEM_BYTES);

    const int GY = ROWS_CAP / 128;  // 1280 M-tiles (blocks beyond M exit early)

    k_meta<<<1, 128>>>(sidx, N);
    k_zeropad<<<ROWS_CAP, 128>>>();
    k_scatter<<<N, 128>>>(emb, sidx);

    // QKV = X @ W_in^T + b_in                      [M, 1536]
    k_tgemm<<<dim3(12, GY), 256, TG_SMEM_BYTES>>>(pX, W_in, b_in, nullptr, pQKV, 1536, 512, 0);

    // attention                                     -> ATT [M, 512]
    k_attn<<<dim3(CAP, 8), 256>>>(pQKV, pATT);

    // TMP = ATT @ W_o^T + b_o + X                  [M, 512]
    k_tgemm<<<dim3(4, GY), 256, TG_SMEM_BYTES>>>(pATT, W_o, b_o, pX, pTMP, 512, 512, 0);

    // Y1 = LN1(TMP) -> X
    k_ln<<<ROWS_CAP, 128>>>(pTMP, ln1g, ln1b, pX);

    // HID = relu(Y1 @ W1^T + b1)                   [M, 1024]
    k_tgemm<<<dim3(8, GY), 256, TG_SMEM_BYTES>>>(pX, W1, b1, nullptr, pHID, 1024, 512, 1);

    // TMP = HID @ W2^T + b2 + Y1                   [M, 512]
    k_tgemm<<<dim3(4, GY), 256, TG_SMEM_BYTES>>>(pHID, W2, b2, pX, pTMP, 512, 1024, 0);

    // X2 = LN2(TMP) -> ATT
    k_ln<<<ROWS_CAP, 128>>>(pTMP, ln2g, ln2b, pATT);

    k_pool<<<64, 512>>>(pATT, out);
}

// round 5
// speedup vs baseline: 2.5192x; 1.4714x over previous
#include <cuda_runtime.h>
#include <math.h>
#include <stdint.h>

// ---------------------------------------------------------------------------
// Problem: D=512, H=8 (e=64), B=64 studies, N=131072 cells.
// Padded layout: row r = n*64 + g. max_n data-dependent; CAP upper bound.
// ---------------------------------------------------------------------------
#define CAP       2560
#define ROWS_CAP  (CAP * 64)   // 163840

__device__ int g_maxn;
__device__ int g_starts[65];
__device__ int g_counts[64];

__device__ float g_X  [(size_t)ROWS_CAP * 512];
__device__ float g_QKV[(size_t)ROWS_CAP * 1536];
__device__ float g_ATT[(size_t)ROWS_CAP * 512];
__device__ float g_TMP[(size_t)ROWS_CAP * 512];
__device__ float g_HID[(size_t)ROWS_CAP * 1024];

// ---------------------------------------------------------------------------
// Meta / scatter / zeropad
// ---------------------------------------------------------------------------
__global__ void k_meta(const int* __restrict__ idx, int N) {
    __shared__ int st[65];
    __shared__ int smax;
    int t = threadIdx.x;
    if (t == 0) smax = 0;
    if (t <= 64) {
        if (t == 64) st[64] = N;
        else {
            int lo = 0, hi = N;
            while (lo < hi) { int mid = (lo + hi) >> 1; if (idx[mid] < t) lo = mid + 1; else hi = mid; }
            st[t] = lo;
        }
    }
    __syncthreads();
    if (t < 64) {
        int c = st[t + 1] - st[t];
        g_starts[t] = st[t];
        g_counts[t] = c;
        atomicMax(&smax, c);
    }
    if (t == 64) g_starts[64] = N;
    __syncthreads();
    if (t == 0) g_maxn = (smax < CAP) ? smax : CAP;
}

// zero the padding rows only: block g handles study g's rows [counts[g], maxn)
__global__ void k_zeropad() {
    int g = blockIdx.x;
    int c0 = g_counts[g];
    int rows = g_maxn - c0;
    if (rows <= 0) return;
    float4 z = make_float4(0.f, 0.f, 0.f, 0.f);
    for (int w = threadIdx.x; w < rows * 128; w += 256) {
        int n = c0 + (w >> 7);
        int j = w & 127;
        ((float4*)(g_X + (size_t)((n << 6) + g) * 512))[j] = z;
    }
}

__global__ void k_scatter(const float* __restrict__ emb, const int* __restrict__ idx) {
    int i = blockIdx.x;
    int g = idx[i];
    int n = i - g_starts[g];
    const float4* s = (const float4*)(emb + (size_t)i * 512);
    float4*       d = (float4*)(g_X + (size_t)(n * 64 + g) * 512);
    d[threadIdx.x] = s[threadIdx.x];
}

// ---------------------------------------------------------------------------
// tf32 tensor-core GEMM, pipelined:
//   C[M,Nc] = A[M,K] * Bw[Nc,K]^T + bias (+resid) (relu)
// BM=BN=128, BK=32. 8 warps, warp tile 64x32 (4x4 m16n8k8).
// 3-stage cp.async.cg gmem->smem (raw fp32), ldmatrix fragment loads,
// cvt.rna.tf32 on fragments, register double-buffer across kk.
// Smem rows padded to 36 words -> LDSM 8-row reads hit distinct banks.
// ---------------------------------------------------------------------------
#define SROW 36
#define TILE_W   (128 * SROW)           // 4608 words per operand tile
#define STAGE_B  (2u * TILE_W * 4u)     // 36864 bytes (A + B)
#define TG_SMEM_BYTES (3u * STAGE_B)    // 110592

__device__ __forceinline__ uint32_t f2tf32(float f) {
    uint32_t r;
    asm("cvt.rna.tf32.f32 %0, %1;" : "=r"(r) : "f"(f));
    return r;
}
__device__ __forceinline__ void mma_tf32(float c[4],
                                         uint32_t a0, uint32_t a1, uint32_t a2, uint32_t a3,
                                         uint32_t b0, uint32_t b1) {
    asm volatile(
        "mma.sync.aligned.m16n8k8.row.col.f32.tf32.tf32.f32 "
        "{%0,%1,%2,%3}, {%4,%5,%6,%7}, {%8,%9}, {%0,%1,%2,%3};"
        : "+f"(c[0]), "+f"(c[1]), "+f"(c[2]), "+f"(c[3])
        : "r"(a0), "r"(a1), "r"(a2), "r"(a3), "r"(b0), "r"(b1));
}
#define LDSM4(f, a) \
    asm volatile("ldmatrix.sync.aligned.m8n8.x4.shared.b16 {%0,%1,%2,%3}, [%4];" \
                 : "=r"((f)[0]), "=r"((f)[1]), "=r"((f)[2]), "=r"((f)[3]) : "r"(a))
#define LDSM2(f, a) \
    asm volatile("ldmatrix.sync.aligned.m8n8.x2.shared.b16 {%0,%1}, [%2];" \
                 : "=r"((f)[0]), "=r"((f)[1]) : "r"(a))

__global__ __launch_bounds__(256, 2)
void k_tgemm(const float* __restrict__ A, const float* __restrict__ Bw,
             const float* __restrict__ bias, const float* __restrict__ resid,
             float* __restrict__ C, int Ncols, int K, int relu)
{
    int M = g_maxn * 64;
    int row0 = blockIdx.y * 128;
    if (row0 >= M) return;
    int col0 = blockIdx.x * 128;

    int tid  = threadIdx.x;
    int lane = tid & 31;
    int wid  = tid >> 5;
    int wm   = wid & 1;        // 2 warp rows x 64
    int wn   = wid >> 1;       // 4 warp cols x 32
    int g    = lane >> 2;
    int tg   = lane & 3;

    extern __shared__ uint32_t sm[];
    uint32_t smb = (uint32_t)__cvta_generic_to_shared(sm);

    const float* Abase = A  + (size_t)row0 * K;
    const float* Bbase = Bw + (size_t)col0 * K;

    // staging coords: per chunk i: row = (tid>>3)+32*i, c4 = tid&7
    int srow = tid >> 3;
    int sc4  = tid & 7;

    // LDSM lane address offsets (bytes)
    uint32_t rowA = (uint32_t)(((wm * 64 + (lane & 15)) * SROW + (lane >> 4) * 4) * 4);
    uint32_t rowB = (uint32_t)(((wn * 32 + (lane & 7)) * SROW + ((lane >> 3) & 1) * 4) * 4);

    float c[4][4][4];
#pragma unroll
    for (int i = 0; i < 4; i++)
#pragma unroll
        for (int j = 0; j < 4; j++)
#pragma unroll
            for (int k = 0; k < 4; k++) c[i][j][k] = 0.f;

    const int KT = K >> 5;

    // ---- stage(kt) : issue 8 cp.async for tile kt into buffer kt%3 ----
#define STAGE(kt_)  do {                                                          \
        int _kt = (kt_);                                                          \
        uint32_t _sb = smb + (uint32_t)(_kt % 3) * STAGE_B;                       \
        int _ko = _kt * 32 + sc4 * 4;                                             \
        _Pragma("unroll")                                                         \
        for (int _i = 0; _i < 4; _i++) {                                          \
            int _row = srow + 32 * _i;                                            \
            uint32_t _d = _sb + (uint32_t)((_row * SROW + sc4 * 4) * 4);          \
            int _ok = (row0 + _row) < M;                                          \
            const float* _sa = Abase + (size_t)(_ok ? _row : 0) * K + _ko;        \
            int _sz = _ok ? 16 : 0;                                               \
            asm volatile("cp.async.cg.shared.global [%0], [%1], 16, %2;"          \
                         :: "r"(_d), "l"(_sa), "r"(_sz));                         \
            uint32_t _d2 = _d + (uint32_t)(TILE_W * 4);                           \
            const float* _sb2 = Bbase + (size_t)_row * K + _ko;                   \
            asm volatile("cp.async.cg.shared.global [%0], [%1], 16;"              \
                         :: "r"(_d2), "l"(_sb2));                                 \
        }                                                                         \
        asm volatile("cp.async.commit_group;");                                   \
    } while (0)

    STAGE(0);
    STAGE(1);

    uint32_t fa[2][4][4], fb[2][4][2];

    for (int kt = 0; kt < KT; kt++) {
        if (kt + 1 < KT) { asm volatile("cp.async.wait_group 1;"); }
        else             { asm volatile("cp.async.wait_group 0;"); }
        __syncthreads();
        if (kt + 2 < KT) STAGE(kt + 2);

        uint32_t ab = smb + (uint32_t)(kt % 3) * STAGE_B;
        uint32_t bb = ab + (uint32_t)(TILE_W * 4);

        // fragments for kk=0
#pragma unroll
        for (int mt = 0; mt < 4; mt++)
            LDSM4(fa[0][mt], ab + rowA + (uint32_t)((mt * 16 * SROW) * 4));
#pragma unroll
        for (int nt = 0; nt < 4; nt++)
            LDSM2(fb[0][nt], bb + rowB + (uint32_t)((nt * 8 * SROW) * 4));

#pragma unroll
        for (int kk = 0; kk < 4; kk++) {
            const int cb = kk & 1, nb = cb ^ 1;
            if (kk < 3) {
#pragma unroll
                for (int mt = 0; mt < 4; mt++)
                    LDSM4(fa[nb][mt], ab + rowA + (uint32_t)(((mt * 16 * SROW) + (kk + 1) * 8) * 4));
#pragma unroll
                for (int nt = 0; nt < 4; nt++)
                    LDSM2(fb[nb][nt], bb + rowB + (uint32_t)(((nt * 8 * SROW) + (kk + 1) * 8) * 4));
            }
            // tf32 round (rna) on current fragments
#pragma unroll
            for (int mt = 0; mt < 4; mt++)
#pragma unroll
                for (int i = 0; i < 4; i++)
                    fa[cb][mt][i] = f2tf32(__uint_as_float(fa[cb][mt][i]));
#pragma unroll
            for (int nt = 0; nt < 4; nt++) {
                fb[cb][nt][0] = f2tf32(__uint_as_float(fb[cb][nt][0]));
                fb[cb][nt][1] = f2tf32(__uint_as_float(fb[cb][nt][1]));
            }
#pragma unroll
            for (int nt = 0; nt < 4; nt++)
#pragma unroll
                for (int mt = 0; mt < 4; mt++)
                    mma_tf32(c[mt][nt],
                             fa[cb][mt][0], fa[cb][mt][1], fa[cb][mt][2], fa[cb][mt][3],
                             fb[cb][nt][0], fb[cb][nt][1]);
        }
    }

    // epilogue: bias (+resid) (relu)
#pragma unroll
    for (int mt = 0; mt < 4; mt++) {
        int r0 = row0 + wm * 64 + mt * 16 + g;
        int r1 = r0 + 8;
#pragma unroll
        for (int nt = 0; nt < 4; nt++) {
            int cc = col0 + wn * 32 + nt * 8 + 2 * tg;
            float2 bv = *(const float2*)(bias + cc);
            if (r0 < M) {
                float2 o = make_float2(c[mt][nt][0] + bv.x, c[mt][nt][1] + bv.y);
                if (resid) {
                    float2 rv = *(const float2*)(resid + (size_t)r0 * Ncols + cc);
                    o.x += rv.x; o.y += rv.y;
                }
                if (relu) { o.x = fmaxf(o.x, 0.f); o.y = fmaxf(o.y, 0.f); }
                *(float2*)(C + (size_t)r0 * Ncols + cc) = o;
            }
            if (r1 < M) {
                float2 o = make_float2(c[mt][nt][2] + bv.x, c[mt][nt][3] + bv.y);
                if (resid) {
                    float2 rv = *(const float2*)(resid + (size_t)r1 * Ncols + cc);
                    o.x += rv.x; o.y += rv.y;
                }
                if (relu) { o.x = fmaxf(o.x, 0.f); o.y = fmaxf(o.y, 0.f); }
                *(float2*)(C + (size_t)r1 * Ncols + cc) = o;
            }
        }
    }
#undef STAGE
}

// ---------------------------------------------------------------------------
// Attention (proven): one block per (position n, head h).
// ---------------------------------------------------------------------------
__global__ __launch_bounds__(256)
void k_attn(const float* __restrict__ QKV, float* __restrict__ ATT) {
    int n = blockIdx.x;
    if (n >= g_maxn) return;
    int h = blockIdx.y;

    __shared__ float Qt[64][64];
    __shared__ float Kt[64][64];
    __shared__ float V [64][64];

    int tid = threadIdx.x;
    size_t base = (size_t)n * 64 * 1536 + (size_t)h * 64;
    for (int idx = tid; idx < 4096; idx += 256) {
        int s = idx >> 6, e = idx & 63;
        size_t rb = base + (size_t)s * 1536 + e;
        Qt[e][s] = QKV[rb];
        Kt[e][s] = QKV[rb + 512];
        V [s][e] = QKV[rb + 1024];
    }
    __syncthreads();

    int s  = tid >> 2;
    int qd = tid & 3;
    int t0 = qd << 4;

    float acc[16];
#pragma unroll
    for (int j = 0; j < 16; j++) acc[j] = 0.f;

#pragma unroll 4
    for (int e = 0; e < 64; e++) {
        float  qv = Qt[e][s];
        float4 k0 = *(const float4*)&Kt[e][t0 + 0];
        float4 k1 = *(const float4*)&Kt[e][t0 + 4];
        float4 k2 = *(const float4*)&Kt[e][t0 + 8];
        float4 k3 = *(const float4*)&Kt[e][t0 + 12];
        acc[0]  = fmaf(qv, k0.x, acc[0]);  acc[1]  = fmaf(qv, k0.y, acc[1]);
        acc[2]  = fmaf(qv, k0.z, acc[2]);  acc[3]  = fmaf(qv, k0.w, acc[3]);
        acc[4]  = fmaf(qv, k1.x, acc[4]);  acc[5]  = fmaf(qv, k1.y, acc[5]);
        acc[6]  = fmaf(qv, k1.z, acc[6]);  acc[7]  = fmaf(qv, k1.w, acc[7]);
        acc[8]  = fmaf(qv, k2.x, acc[8]);  acc[9]  = fmaf(qv, k2.y, acc[9]);
        acc[10] = fmaf(qv, k2.z, acc[10]); acc[11] = fmaf(qv, k2.w, acc[11]);
        acc[12] = fmaf(qv, k3.x, acc[12]); acc[13] = fmaf(qv, k3.y, acc[13]);
        acc[14] = fmaf(qv, k3.z, acc[14]); acc[15] = fmaf(qv, k3.w, acc[15]);
    }

    float mx = -1e30f;
#pragma unroll
    for (int j = 0; j < 16; j++) {
        float v = acc[j] * 0.125f;
        if (g_counts[t0 + j] <= n) v = -1e30f;
        acc[j] = v;
        mx = fmaxf(mx, v);
    }
    mx = fmaxf(mx, __shfl_xor_sync(0xffffffffu, mx, 1, 4));
    mx = fmaxf(mx, __shfl_xor_sync(0xffffffffu, mx, 2, 4));
    float sum = 0.f;
#pragma unroll
    for (int j = 0; j < 16; j++) { float p = __expf(acc[j] - mx); acc[j] = p; sum += p; }
    sum += __shfl_xor_sync(0xffffffffu, sum, 1, 4);
    sum += __shfl_xor_sync(0xffffffffu, sum, 2, 4);
    float inv = 1.f / sum;
#pragma unroll
    for (int j = 0; j < 16; j++) acc[j] *= inv;

    float o[16];
#pragma unroll
    for (int j = 0; j < 16; j++) o[j] = 0.f;
    int e0 = qd << 4;
#pragma unroll
    for (int tq = 0; tq < 4; tq++) {
#pragma unroll
        for (int j2 = 0; j2 < 16; j2++) {
            float a = __shfl_sync(0xffffffffu, acc[j2], tq, 4);
            const float* vr = &V[tq * 16 + j2][e0];
            float4 v0 = *(const float4*)(vr + 0);
            float4 v1 = *(const float4*)(vr + 4);
            float4 v2 = *(const float4*)(vr + 8);
            float4 v3 = *(const float4*)(vr + 12);
            o[0]  = fmaf(a, v0.x, o[0]);  o[1]  = fmaf(a, v0.y, o[1]);
            o[2]  = fmaf(a, v0.z, o[2]);  o[3]  = fmaf(a, v0.w, o[3]);
            o[4]  = fmaf(a, v1.x, o[4]);  o[5]  = fmaf(a, v1.y, o[5]);
            o[6]  = fmaf(a, v1.z, o[6]);  o[7]  = fmaf(a, v1.w, o[7]);
            o[8]  = fmaf(a, v2.x, o[8]);  o[9]  = fmaf(a, v2.y, o[9]);
            o[10] = fmaf(a, v2.z, o[10]); o[11] = fmaf(a, v2.w, o[11]);
            o[12] = fmaf(a, v3.x, o[12]); o[13] = fmaf(a, v3.y, o[13]);
            o[14] = fmaf(a, v3.z, o[14]); o[15] = fmaf(a, v3.w, o[15]);
        }
    }

    float* op = ATT + (size_t)(n * 64 + s) * 512 + (size_t)h * 64 + e0;
    *(float4*)(op + 0)  = make_float4(o[0],  o[1],  o[2],  o[3]);
    *(float4*)(op + 4)  = make_float4(o[4],  o[5],  o[6],  o[7]);
    *(float4*)(op + 8)  = make_float4(o[8],  o[9],  o[10], o[11]);
    *(float4*)(op + 12) = make_float4(o[12], o[13], o[14], o[15]);
}

// ---------------------------------------------------------------------------
// LayerNorm + pool (proven)
// ---------------------------------------------------------------------------
__global__ void k_ln(const float* __restrict__ in, const float* __restrict__ gam,
                     const float* __restrict__ bet, float* __restrict__ outp) {
    int r = blockIdx.x;
    if (r >= g_maxn * 64) return;
    int t = threadIdx.x;
    float4 v = ((const float4*)(in + (size_t)r * 512))[t];
    float s  = v.x + v.y + v.z + v.w;
    float ss = fmaf(v.x, v.x, fmaf(v.y, v.y, fmaf(v.z, v.z, v.w * v.w)));
#pragma unroll
    for (int o = 16; o; o >>= 1) {
        s  += __shfl_xor_sync(0xffffffffu, s,  o);
        ss += __shfl_xor_sync(0xffffffffu, ss, o);
    }
    __shared__ float sh[8];
    if ((t & 31) == 0) { sh[t >> 5] = s; sh[4 + (t >> 5)] = ss; }
    __syncthreads();
    s  = sh[0] + sh[1] + sh[2] + sh[3];
    ss = sh[4] + sh[5] + sh[6] + sh[7];
    float mean = s * (1.f / 512.f);
    float var  = ss * (1.f / 512.f) - mean * mean;
    float inv  = rsqrtf(var + 1e-5f);
    float4 g4 = ((const float4*)gam)[t];
    float4 b4 = ((const float4*)bet)[t];
    float4 o4;
    o4.x = (v.x - mean) * inv * g4.x + b4.x;
    o4.y = (v.y - mean) * inv * g4.y + b4.y;
    o4.z = (v.z - mean) * inv * g4.z + b4.z;
    o4.w = (v.w - mean) * inv * g4.w + b4.w;
    ((float4*)(outp + (size_t)r * 512))[t] = o4;
}

__global__ void k_pool(const float* __restrict__ Xf, float* __restrict__ out) {
    int g = blockIdx.x;
    int d = threadIdx.x;
    int mx = g_maxn;
    const float* p = Xf + (size_t)g * 512 + d;
    const size_t stride = 64 * 512;
    float s0 = 0.f, s1 = 0.f, s2 = 0.f, s3 = 0.f;
    int n = 0;
    for (; n + 4 <= mx; n += 4) {
        s0 += p[(size_t)(n + 0) * stride];
        s1 += p[(size_t)(n + 1) * stride];
        s2 += p[(size_t)(n + 2) * stride];
        s3 += p[(size_t)(n + 3) * stride];
    }
    for (; n < mx; n++) s0 += p[(size_t)n * stride];
    out[g * 512 + d] = (s0 + s1 + s2 + s3) / (float)mx;
}

// ---------------------------------------------------------------------------
// Launch
// ---------------------------------------------------------------------------
extern "C" void kernel_launch(void* const* d_in, const int* in_sizes, int n_in,
                              void* d_out, int out_size) {
    const float* emb  = (const float*)d_in[0];
    const int*   sidx = (const int*)  d_in[1];
    const float* W_in = (const float*)d_in[2];
    const float* b_in = (const float*)d_in[3];
    const float* W_o  = (const float*)d_in[4];
    const float* b_o  = (const float*)d_in[5];
    const float* ln1g = (const float*)d_in[6];
    const float* ln1b = (const float*)d_in[7];
    const float* W1   = (const float*)d_in[8];
    const float* b1   = (const float*)d_in[9];
    const float* W2   = (const float*)d_in[10];
    const float* b2   = (const float*)d_in[11];
    const float* ln2g = (const float*)d_in[12];
    const float* ln2b = (const float*)d_in[13];
    float* out = (float*)d_out;
    (void)n_in; (void)out_size;

    int N = in_sizes[0] / 512;

    float *pX, *pQKV, *pATT, *pTMP, *pHID;
    cudaGetSymbolAddress((void**)&pX,   g_X);
    cudaGetSymbolAddress((void**)&pQKV, g_QKV);
    cudaGetSymbolAddress((void**)&pATT, g_ATT);
    cudaGetSymbolAddress((void**)&pTMP, g_TMP);
    cudaGetSymbolAddress((void**)&pHID, g_HID);

    cudaFuncSetAttribute(k_tgemm, cudaFuncAttributeMaxDynamicSharedMemorySize,
                         (int)TG_SMEM_BYTES);

    const int GY = ROWS_CAP / 128;  // 1280 M-tiles (blocks beyond M exit early)

    k_meta<<<1, 128>>>(sidx, N);
    k_zeropad<<<64, 256>>>();
    k_scatter<<<N, 128>>>(emb, sidx);

    // QKV = X @ W_in^T + b_in                      [M, 1536]
    k_tgemm<<<dim3(12, GY), 256, TG_SMEM_BYTES>>>(pX, W_in, b_in, nullptr, pQKV, 1536, 512, 0);

    // attention                                     -> ATT [M, 512]
    k_attn<<<dim3(CAP, 8), 256>>>(pQKV, pATT);

    // TMP = ATT @ W_o^T + b_o + X                  [M, 512]
    k_tgemm<<<dim3(4, GY), 256, TG_SMEM_BYTES>>>(pATT, W_o, b_o, pX, pTMP, 512, 512, 0);

    // Y1 = LN1(TMP) -> X
    k_ln<<<ROWS_CAP, 128>>>(pTMP, ln1g, ln1b, pX);

    // HID = relu(Y1 @ W1^T + b1)                   [M, 1024]
    k_tgemm<<<dim3(8, GY), 256, TG_SMEM_BYTES>>>(pX, W1, b1, nullptr, pHID, 1024, 512, 1);

    // TMP = HID @ W2^T + b2 + Y1                   [M, 1024->512]
    k_tgemm<<<dim3(4, GY), 256, TG_SMEM_BYTES>>>(pHID, W2, b2, pX, pTMP, 512, 1024, 0);

    // X2 = LN2(TMP) -> ATT
    k_ln<<<ROWS_CAP, 128>>>(pTMP, ln2g, ln2b, pATT);

    k_pool<<<64, 512>>>(pATT, out);
}

// round 6
// speedup vs baseline: 2.6220x; 1.0408x over previous
#include <cuda_runtime.h>
#include <math.h>
#include <stdint.h>

// ---------------------------------------------------------------------------
// Problem: D=512, H=8 (e=64), B=64 studies, N=131072 cells.
// Padded layout: row r = n*64 + g. max_n data-dependent; CAP upper bound.
// All GEMM operands are tf32-rounded AT THE PRODUCER, so the GEMM mainloop
// feeds raw fp32 bits to mma.sync (HW truncation == identity on them).
// ---------------------------------------------------------------------------
#define CAP       2560
#define ROWS_CAP  (CAP * 64)   // 163840

__device__ int g_maxn;
__device__ int g_starts[65];
__device__ int g_counts[64];

__device__ float g_X  [(size_t)ROWS_CAP * 512];
__device__ float g_QKV[(size_t)ROWS_CAP * 1536];
__device__ float g_ATT[(size_t)ROWS_CAP * 512];
__device__ float g_TMP[(size_t)ROWS_CAP * 512];
__device__ float g_HID[(size_t)ROWS_CAP * 1024];
__device__ float g_Wr [2097152];   // rounded W_in | W_o | W1 | W2

__device__ __forceinline__ uint32_t f2tf32(float f) {
    uint32_t r;
    asm("cvt.rna.tf32.f32 %0, %1;" : "=r"(r) : "f"(f));
    return r;
}
__device__ __forceinline__ float rnd_tf32(float f) {
    return __uint_as_float(f2tf32(f));
}

// ---------------------------------------------------------------------------
// Meta / zeropad / scatter / weight rounding
// ---------------------------------------------------------------------------
__global__ void k_meta(const int* __restrict__ idx, int N) {
    __shared__ int st[65];
    __shared__ int smax;
    int t = threadIdx.x;
    if (t == 0) smax = 0;
    if (t <= 64) {
        if (t == 64) st[64] = N;
        else {
            int lo = 0, hi = N;
            while (lo < hi) { int mid = (lo + hi) >> 1; if (idx[mid] < t) lo = mid + 1; else hi = mid; }
            st[t] = lo;
        }
    }
    __syncthreads();
    if (t < 64) {
        int c = st[t + 1] - st[t];
        g_starts[t] = st[t];
        g_counts[t] = c;
        atomicMax(&smax, c);
    }
    if (t == 64) g_starts[64] = N;
    __syncthreads();
    if (t == 0) g_maxn = (smax < CAP) ? smax : CAP;
}

__global__ void k_zeropad() {
    int g = blockIdx.x;
    int c0 = g_counts[g];
    int rows = g_maxn - c0;
    if (rows <= 0) return;
    float4 z = make_float4(0.f, 0.f, 0.f, 0.f);
    for (int w = threadIdx.x; w < rows * 128; w += 256) {
        int n = c0 + (w >> 7);
        int j = w & 127;
        ((float4*)(g_X + (size_t)((n << 6) + g) * 512))[j] = z;
    }
}

// scatter + tf32-round (X is a GEMM A-operand)
__global__ void k_scatter(const float* __restrict__ emb, const int* __restrict__ idx) {
    int i = blockIdx.x;
    int g = idx[i];
    int n = i - g_starts[g];
    float4 v = ((const float4*)(emb + (size_t)i * 512))[threadIdx.x];
    v.x = rnd_tf32(v.x); v.y = rnd_tf32(v.y); v.z = rnd_tf32(v.z); v.w = rnd_tf32(v.w);
    ((float4*)(g_X + (size_t)(n * 64 + g) * 512))[threadIdx.x] = v;
}

// round a weight matrix into g_Wr
__global__ void k_roundw(const float* __restrict__ s, float* __restrict__ d, int n4) {
    int i = blockIdx.x * 256 + threadIdx.x;
    if (i >= n4) return;
    float4 v = ((const float4*)s)[i];
    v.x = rnd_tf32(v.x); v.y = rnd_tf32(v.y); v.z = rnd_tf32(v.z); v.w = rnd_tf32(v.w);
    ((float4*)d)[i] = v;
}

// ---------------------------------------------------------------------------
// tf32 tensor-core GEMM, pipelined. Operands pre-rounded -> no CVT in loop.
// BM=BN=128, BK=32. 8 warps, warp tile 64x32 (4x4 m16n8k8).
// 3-stage cp.async.cg, ldmatrix x4 for A and B (paired nt), reg double-buffer.
// ---------------------------------------------------------------------------
#define SROW 36
#define TILE_W   (128 * SROW)
#define STAGE_B  (2u * TILE_W * 4u)     // 36864
#define TG_SMEM_BYTES (3u * STAGE_B)    // 110592

__device__ __forceinline__ void mma_tf32(float c[4],
                                         uint32_t a0, uint32_t a1, uint32_t a2, uint32_t a3,
                                         uint32_t b0, uint32_t b1) {
    asm volatile(
        "mma.sync.aligned.m16n8k8.row.col.f32.tf32.tf32.f32 "
        "{%0,%1,%2,%3}, {%4,%5,%6,%7}, {%8,%9}, {%0,%1,%2,%3};"
        : "+f"(c[0]), "+f"(c[1]), "+f"(c[2]), "+f"(c[3])
        : "r"(a0), "r"(a1), "r"(a2), "r"(a3), "r"(b0), "r"(b1));
}
#define LDSM4(f, a) \
    asm volatile("ldmatrix.sync.aligned.m8n8.x4.shared.b16 {%0,%1,%2,%3}, [%4];" \
                 : "=r"((f)[0]), "=r"((f)[1]), "=r"((f)[2]), "=r"((f)[3]) : "r"(a))

__global__ __launch_bounds__(256, 2)
void k_tgemm(const float* __restrict__ A, const float* __restrict__ Bw,
             const float* __restrict__ bias, const float* __restrict__ resid,
             float* __restrict__ C, int Ncols, int K, int relu, int round_out)
{
    int M = g_maxn * 64;
    int row0 = blockIdx.y * 128;
    if (row0 >= M) return;
    int col0 = blockIdx.x * 128;

    int tid  = threadIdx.x;
    int lane = tid & 31;
    int wid  = tid >> 5;
    int wm   = wid & 1;
    int wn   = wid >> 1;
    int g    = lane >> 2;
    int tg   = lane & 3;

    extern __shared__ uint32_t sm[];
    uint32_t smb = (uint32_t)__cvta_generic_to_shared(sm);

    const float* Abase = A  + (size_t)row0 * K;
    const float* Bbase = Bw + (size_t)col0 * K;

    int srow = tid >> 3;
    int sc4  = tid & 7;

    // LDSM lane byte offsets
    uint32_t rowA = (uint32_t)(((wm * 64 + (lane & 15)) * SROW + (lane >> 4) * 4) * 4);
    // B x4: lanes 0-15 -> nt-pair row group p*16 rows 0-7 (k halves), lanes 16-31 -> rows 8-15
    uint32_t rowB = (uint32_t)(((wn * 32 + (lane & 7) + (lane >> 4) * 8) * SROW
                                + ((lane >> 3) & 1) * 4) * 4);

    float c[4][4][4];
#pragma unroll
    for (int i = 0; i < 4; i++)
#pragma unroll
        for (int j = 0; j < 4; j++)
#pragma unroll
            for (int k = 0; k < 4; k++) c[i][j][k] = 0.f;

    const int KT = K >> 5;

#define STAGE(kt_)  do {                                                          \
        int _kt = (kt_);                                                          \
        uint32_t _sb = smb + (uint32_t)(_kt % 3) * STAGE_B;                       \
        int _ko = _kt * 32 + sc4 * 4;                                             \
        _Pragma("unroll")                                                         \
        for (int _i = 0; _i < 4; _i++) {                                          \
            int _row = srow + 32 * _i;                                            \
            uint32_t _d = _sb + (uint32_t)((_row * SROW + sc4 * 4) * 4);          \
            int _ok = (row0 + _row) < M;                                          \
            const float* _sa = Abase + (size_t)(_ok ? _row : 0) * K + _ko;        \
            int _sz = _ok ? 16 : 0;                                               \
            asm volatile("cp.async.cg.shared.global [%0], [%1], 16, %2;"          \
                         :: "r"(_d), "l"(_sa), "r"(_sz));                         \
            uint32_t _d2 = _d + (uint32_t)(TILE_W * 4);                           \
            const float* _sb2 = Bbase + (size_t)_row * K + _ko;                   \
            asm volatile("cp.async.cg.shared.global [%0], [%1], 16;"              \
                         :: "r"(_d2), "l"(_sb2));                                 \
        }                                                                         \
        asm volatile("cp.async.commit_group;");                                   \
    } while (0)

    STAGE(0);
    STAGE(1);

    uint32_t fa[2][4][4], fb[2][2][4];

    for (int kt = 0; kt < KT; kt++) {
        if (kt + 1 < KT) { asm volatile("cp.async.wait_group 1;"); }
        else             { asm volatile("cp.async.wait_group 0;"); }
        __syncthreads();
        if (kt + 2 < KT) STAGE(kt + 2);

        uint32_t aB = smb + (uint32_t)(kt % 3) * STAGE_B + rowA;
        uint32_t bB = smb + (uint32_t)(kt % 3) * STAGE_B + (uint32_t)(TILE_W * 4) + rowB;

        // fragments for kk=0
#pragma unroll
        for (int mt = 0; mt < 4; mt++)
            LDSM4(fa[0][mt], aB + (uint32_t)(mt * 16 * SROW * 4));
#pragma unroll
        for (int p = 0; p < 2; p++)
            LDSM4(fb[0][p], bB + (uint32_t)(p * 16 * SROW * 4));

#pragma unroll
        for (int kk = 0; kk < 4; kk++) {
            const int cb = kk & 1, nb = cb ^ 1;
            if (kk < 3) {
#pragma unroll
                for (int mt = 0; mt < 4; mt++)
                    LDSM4(fa[nb][mt], aB + (uint32_t)((mt * 16 * SROW + (kk + 1) * 8) * 4));
#pragma unroll
                for (int p = 0; p < 2; p++)
                    LDSM4(fb[nb][p], bB + (uint32_t)((p * 16 * SROW + (kk + 1) * 8) * 4));
            }
#pragma unroll
            for (int p = 0; p < 2; p++) {
#pragma unroll
                for (int mt = 0; mt < 4; mt++)
                    mma_tf32(c[mt][2 * p],
                             fa[cb][mt][0], fa[cb][mt][1], fa[cb][mt][2], fa[cb][mt][3],
                             fb[cb][p][0], fb[cb][p][1]);
#pragma unroll
                for (int mt = 0; mt < 4; mt++)
                    mma_tf32(c[mt][2 * p + 1],
                             fa[cb][mt][0], fa[cb][mt][1], fa[cb][mt][2], fa[cb][mt][3],
                             fb[cb][p][2], fb[cb][p][3]);
            }
        }
    }

    // epilogue: bias (+resid) (relu) (tf32 round if output feeds a GEMM)
#pragma unroll
    for (int mt = 0; mt < 4; mt++) {
        int r0 = row0 + wm * 64 + mt * 16 + g;
        int r1 = r0 + 8;
#pragma unroll
        for (int nt = 0; nt < 4; nt++) {
            int cc = col0 + wn * 32 + nt * 8 + 2 * tg;
            float2 bv = *(const float2*)(bias + cc);
            if (r0 < M) {
                float2 o = make_float2(c[mt][nt][0] + bv.x, c[mt][nt][1] + bv.y);
                if (resid) {
                    float2 rv = *(const float2*)(resid + (size_t)r0 * Ncols + cc);
                    o.x += rv.x; o.y += rv.y;
                }
                if (relu) { o.x = fmaxf(o.x, 0.f); o.y = fmaxf(o.y, 0.f); }
                if (round_out) { o.x = rnd_tf32(o.x); o.y = rnd_tf32(o.y); }
                *(float2*)(C + (size_t)r0 * Ncols + cc) = o;
            }
            if (r1 < M) {
                float2 o = make_float2(c[mt][nt][2] + bv.x, c[mt][nt][3] + bv.y);
                if (resid) {
                    float2 rv = *(const float2*)(resid + (size_t)r1 * Ncols + cc);
                    o.x += rv.x; o.y += rv.y;
                }
                if (relu) { o.x = fmaxf(o.x, 0.f); o.y = fmaxf(o.y, 0.f); }
                if (round_out) { o.x = rnd_tf32(o.x); o.y = rnd_tf32(o.y); }
                *(float2*)(C + (size_t)r1 * Ncols + cc) = o;
            }
        }
    }
#undef STAGE
}

// ---------------------------------------------------------------------------
// Attention: one block per (position n, head h). Output tf32-rounded
// (ATT is the A-operand of the W_o GEMM).
// ---------------------------------------------------------------------------
__global__ __launch_bounds__(256)
void k_attn(const float* __restrict__ QKV, float* __restrict__ ATT) {
    int n = blockIdx.x;
    if (n >= g_maxn) return;
    int h = blockIdx.y;

    __shared__ float Qt[64][64];
    __shared__ float Kt[64][64];
    __shared__ float V [64][64];

    int tid = threadIdx.x;
    size_t base = (size_t)n * 64 * 1536 + (size_t)h * 64;
    for (int idx = tid; idx < 4096; idx += 256) {
        int s = idx >> 6, e = idx & 63;
        size_t rb = base + (size_t)s * 1536 + e;
        Qt[e][s] = QKV[rb];
        Kt[e][s] = QKV[rb + 512];
        V [s][e] = QKV[rb + 1024];
    }
    __syncthreads();

    int s  = tid >> 2;
    int qd = tid & 3;
    int t0 = qd << 4;

    float acc[16];
#pragma unroll
    for (int j = 0; j < 16; j++) acc[j] = 0.f;

#pragma unroll 4
    for (int e = 0; e < 64; e++) {
        float  qv = Qt[e][s];
        float4 k0 = *(const float4*)&Kt[e][t0 + 0];
        float4 k1 = *(const float4*)&Kt[e][t0 + 4];
        float4 k2 = *(const float4*)&Kt[e][t0 + 8];
        float4 k3 = *(const float4*)&Kt[e][t0 + 12];
        acc[0]  = fmaf(qv, k0.x, acc[0]);  acc[1]  = fmaf(qv, k0.y, acc[1]);
        acc[2]  = fmaf(qv, k0.z, acc[2]);  acc[3]  = fmaf(qv, k0.w, acc[3]);
        acc[4]  = fmaf(qv, k1.x, acc[4]);  acc[5]  = fmaf(qv, k1.y, acc[5]);
        acc[6]  = fmaf(qv, k1.z, acc[6]);  acc[7]  = fmaf(qv, k1.w, acc[7]);
        acc[8]  = fmaf(qv, k2.x, acc[8]);  acc[9]  = fmaf(qv, k2.y, acc[9]);
        acc[10] = fmaf(qv, k2.z, acc[10]); acc[11] = fmaf(qv, k2.w, acc[11]);
        acc[12] = fmaf(qv, k3.x, acc[12]); acc[13] = fmaf(qv, k3.y, acc[13]);
        acc[14] = fmaf(qv, k3.z, acc[14]); acc[15] = fmaf(qv, k3.w, acc[15]);
    }

    float mx = -1e30f;
#pragma unroll
    for (int j = 0; j < 16; j++) {
        float v = acc[j] * 0.125f;
        if (g_counts[t0 + j] <= n) v = -1e30f;
        acc[j] = v;
        mx = fmaxf(mx, v);
    }
    mx = fmaxf(mx, __shfl_xor_sync(0xffffffffu, mx, 1, 4));
    mx = fmaxf(mx, __shfl_xor_sync(0xffffffffu, mx, 2, 4));
    float sum = 0.f;
#pragma unroll
    for (int j = 0; j < 16; j++) { float p = __expf(acc[j] - mx); acc[j] = p; sum += p; }
    sum += __shfl_xor_sync(0xffffffffu, sum, 1, 4);
    sum += __shfl_xor_sync(0xffffffffu, sum, 2, 4);
    float inv = 1.f / sum;
#pragma unroll
    for (int j = 0; j < 16; j++) acc[j] *= inv;

    float o[16];
#pragma unroll
    for (int j = 0; j < 16; j++) o[j] = 0.f;
    int e0 = qd << 4;
#pragma unroll
    for (int tq = 0; tq < 4; tq++) {
#pragma unroll
        for (int j2 = 0; j2 < 16; j2++) {
            float a = __shfl_sync(0xffffffffu, acc[j2], tq, 4);
            const float* vr = &V[tq * 16 + j2][e0];
            float4 v0 = *(const float4*)(vr + 0);
            float4 v1 = *(const float4*)(vr + 4);
            float4 v2 = *(const float4*)(vr + 8);
            float4 v3 = *(const float4*)(vr + 12);
            o[0]  = fmaf(a, v0.x, o[0]);  o[1]  = fmaf(a, v0.y, o[1]);
            o[2]  = fmaf(a, v0.z, o[2]);  o[3]  = fmaf(a, v0.w, o[3]);
            o[4]  = fmaf(a, v1.x, o[4]);  o[5]  = fmaf(a, v1.y, o[5]);
            o[6]  = fmaf(a, v1.z, o[6]);  o[7]  = fmaf(a, v1.w, o[7]);
            o[8]  = fmaf(a, v2.x, o[8]);  o[9]  = fmaf(a, v2.y, o[9]);
            o[10] = fmaf(a, v2.z, o[10]); o[11] = fmaf(a, v2.w, o[11]);
            o[12] = fmaf(a, v3.x, o[12]); o[13] = fmaf(a, v3.y, o[13]);
            o[14] = fmaf(a, v3.z, o[14]); o[15] = fmaf(a, v3.w, o[15]);
        }
    }

#pragma unroll
    for (int j = 0; j < 16; j++) o[j] = rnd_tf32(o[j]);

    float* op = ATT + (size_t)(n * 64 + s) * 512 + (size_t)h * 64 + e0;
    *(float4*)(op + 0)  = make_float4(o[0],  o[1],  o[2],  o[3]);
    *(float4*)(op + 4)  = make_float4(o[4],  o[5],  o[6],  o[7]);
    *(float4*)(op + 8)  = make_float4(o[8],  o[9],  o[10], o[11]);
    *(float4*)(op + 12) = make_float4(o[12], o[13], o[14], o[15]);
}

// ---------------------------------------------------------------------------
// LayerNorm (optionally tf32-round output) + pool
// ---------------------------------------------------------------------------
__global__ void k_ln(const float* __restrict__ in, const float* __restrict__ gam,
                     const float* __restrict__ bet, float* __restrict__ outp, int rnd) {
    int r = blockIdx.x;
    if (r >= g_maxn * 64) return;
    int t = threadIdx.x;
    float4 v = ((const float4*)(in + (size_t)r * 512))[t];
    float s  = v.x + v.y + v.z + v.w;
    float ss = fmaf(v.x, v.x, fmaf(v.y, v.y, fmaf(v.z, v.z, v.w * v.w)));
#pragma unroll
    for (int o = 16; o; o >>= 1) {
        s  += __shfl_xor_sync(0xffffffffu, s,  o);
        ss += __shfl_xor_sync(0xffffffffu, ss, o);
    }
    __shared__ float sh[8];
    if ((t & 31) == 0) { sh[t >> 5] = s; sh[4 + (t >> 5)] = ss; }
    __syncthreads();
    s  = sh[0] + sh[1] + sh[2] + sh[3];
    ss = sh[4] + sh[5] + sh[6] + sh[7];
    float mean = s * (1.f / 512.f);
    float var  = ss * (1.f / 512.f) - mean * mean;
    float inv  = rsqrtf(var + 1e-5f);
    float4 g4 = ((const float4*)gam)[t];
    float4 b4 = ((const float4*)bet)[t];
    float4 o4;
    o4.x = (v.x - mean) * inv * g4.x + b4.x;
    o4.y = (v.y - mean) * inv * g4.y + b4.y;
    o4.z = (v.z - mean) * inv * g4.z + b4.z;
    o4.w = (v.w - mean) * inv * g4.w + b4.w;
    if (rnd) {
        o4.x = rnd_tf32(o4.x); o4.y = rnd_tf32(o4.y);
        o4.z = rnd_tf32(o4.z); o4.w = rnd_tf32(o4.w);
    }
    ((float4*)(outp + (size_t)r * 512))[t] = o4;
}

__global__ void k_pool(const float* __restrict__ Xf, float* __restrict__ out) {
    int g = blockIdx.x;
    int d = threadIdx.x;
    int mx = g_maxn;
    const float* p = Xf + (size_t)g * 512 + d;
    const size_t stride = 64 * 512;
    float s0 = 0.f, s1 = 0.f, s2 = 0.f, s3 = 0.f;
    int n = 0;
    for (; n + 4 <= mx; n += 4) {
        s0 += p[(size_t)(n + 0) * stride];
        s1 += p[(size_t)(n + 1) * stride];
        s2 += p[(size_t)(n + 2) * stride];
        s3 += p[(size_t)(n + 3) * stride];
    }
    for (; n < mx; n++) s0 += p[(size_t)n * stride];
    out[g * 512 + d] = (s0 + s1 + s2 + s3) / (float)mx;
}

// ---------------------------------------------------------------------------
// Launch
// ---------------------------------------------------------------------------
extern "C" void kernel_launch(void* const* d_in, const int* in_sizes, int n_in,
                              void* d_out, int out_size) {
    const float* emb  = (const float*)d_in[0];
    const int*   sidx = (const int*)  d_in[1];
    const float* W_in = (const float*)d_in[2];
    const float* b_in = (const float*)d_in[3];
    const float* W_o  = (const float*)d_in[4];
    const float* b_o  = (const float*)d_in[5];
    const float* ln1g = (const float*)d_in[6];
    const float* ln1b = (const float*)d_in[7];
    const float* W1   = (const float*)d_in[8];
    const float* b1   = (const float*)d_in[9];
    const float* W2   = (const float*)d_in[10];
    const float* b2   = (const float*)d_in[11];
    const float* ln2g = (const float*)d_in[12];
    const float* ln2b = (const float*)d_in[13];
    float* out = (float*)d_out;
    (void)n_in; (void)out_size;

    int N = in_sizes[0] / 512;

    float *pX, *pQKV, *pATT, *pTMP, *pHID, *pWr;
    cudaGetSymbolAddress((void**)&pX,   g_X);
    cudaGetSymbolAddress((void**)&pQKV, g_QKV);
    cudaGetSymbolAddress((void**)&pATT, g_ATT);
    cudaGetSymbolAddress((void**)&pTMP, g_TMP);
    cudaGetSymbolAddress((void**)&pHID, g_HID);
    cudaGetSymbolAddress((void**)&pWr,  g_Wr);

    float* rWin = pWr;                 // 786432
    float* rWo  = pWr + 786432;        // 262144
    float* rW1  = pWr + 1048576;       // 524288
    float* rW2  = pWr + 1572864;       // 524288

    cudaFuncSetAttribute(k_tgemm, cudaFuncAttributeMaxDynamicSharedMemorySize,
                         (int)TG_SMEM_BYTES);

    const int GY = ROWS_CAP / 128;

    k_meta<<<1, 128>>>(sidx, N);
    k_zeropad<<<64, 256>>>();
    k_scatter<<<N, 128>>>(emb, sidx);
    k_roundw<<<768, 256>>>(W_in, rWin, 196608);
    k_roundw<<<256, 256>>>(W_o,  rWo,   65536);
    k_roundw<<<512, 256>>>(W1,   rW1,  131072);
    k_roundw<<<512, 256>>>(W2,   rW2,  131072);

    // QKV = X @ W_in^T + b_in                      [M, 1536]
    k_tgemm<<<dim3(12, GY), 256, TG_SMEM_BYTES>>>(pX, rWin, b_in, nullptr, pQKV, 1536, 512, 0, 0);

    // attention                                     -> ATT [M, 512] (rounded)
    k_attn<<<dim3(CAP, 8), 256>>>(pQKV, pATT);

    // TMP = ATT @ W_o^T + b_o + X                  [M, 512]
    k_tgemm<<<dim3(4, GY), 256, TG_SMEM_BYTES>>>(pATT, rWo, b_o, pX, pTMP, 512, 512, 0, 0);

    // Y1 = LN1(TMP) -> X (rounded: GEMM A-operand + residual)
    k_ln<<<ROWS_CAP, 128>>>(pTMP, ln1g, ln1b, pX, 1);

    // HID = relu(Y1 @ W1^T + b1)                   [M, 1024] (rounded)
    k_tgemm<<<dim3(8, GY), 256, TG_SMEM_BYTES>>>(pX, rW1, b1, nullptr, pHID, 1024, 512, 1, 1);

    // TMP = HID @ W2^T + b2 + Y1                   [M, 512]
    k_tgemm<<<dim3(4, GY), 256, TG_SMEM_BYTES>>>(pHID, rW2, b2, pX, pTMP, 512, 1024, 0, 0);

    // X2 = LN2(TMP) -> ATT (no rounding; feeds pool only)
    k_ln<<<ROWS_CAP, 128>>>(pTMP, ln2g, ln2b, pATT, 0);

    k_pool<<<64, 512>>>(pATT, out);
}